// round 2
// baseline (speedup 1.0000x reference)
#include <cuda_runtime.h>

#define WW 512
#define HH 512
#define DD 64
#define NN 2
#define HS 32
#define SQRT2F 1.41421356237309515f

// Zero the scalar output (d_out is poisoned to 0xAA by the harness).
__global__ void hess_init_kernel(float* out) { out[0] = 0.0f; }

// One block = one (n, d) slab pair x one 32-row strip of h.
// Each thread owns 4 consecutive w via float4. Rows roll through registers:
// per base row h we only load row (d,h+2), (d+1,h+1), (d+2,h) fresh.
__global__ __launch_bounds__(128)
void hess_kernel(const float* __restrict__ x, float* __restrict__ out) {
    const int tid  = threadIdx.x;
    const int lane = tid & 31;
    const int w0   = tid << 2;            // 128 threads * 4 = 512 = WW
    const int h0   = blockIdx.x * HS;
    const int d    = blockIdx.y;
    const int n    = blockIdx.z;

    const size_t slab = (size_t)HH * WW;
    const float* p0 = x + (size_t)(n * DD + d) * slab;   // slab d
    const bool hd1 = (d + 1 < DD);
    const bool hd2 = (d + 2 < DD);
    const float* p1 = p0 + (hd1 ? slab : 0);             // slab d+1 (clamped)
    const float* p2 = p1 + (hd2 ? slab : 0);             // slab d+2 (clamped)

    const float wzz = hd2 ? 0.5f   : 0.0f;   // CONTIZ^2
    const float wxz = hd1 ? SQRT2F : 0.0f;   // 2*CONTIZ (xz and yz weight)

    float acc = 0.0f;

    // Preload rolling rows: A = (d,h0), B = (d,h0+1), P = (d+1,h0)
    float4 A = *(const float4*)(p0 + (size_t)h0 * WW + w0);
    const int hb0 = (h0 + 1 < HH) ? h0 + 1 : HH - 1;
    float4 B = *(const float4*)(p0 + (size_t)hb0 * WW + w0);
    float4 P = *(const float4*)(p1 + (size_t)h0 * WW + w0);

    #pragma unroll 4
    for (int h = h0; h < h0 + HS; ++h) {
        const int hc1 = (h + 1 < HH) ? h + 1 : HH - 1;
        const int hc2 = (h + 2 < HH) ? h + 2 : HH - 1;
        float4 C = *(const float4*)(p0 + (size_t)hc2 * WW + w0);  // (d,   h+2)
        float4 R = *(const float4*)(p1 + (size_t)hc1 * WW + w0);  // (d+1, h+1)
        float4 Q = *(const float4*)(p2 + (size_t)h   * WW + w0);  // (d+2, h  )

        // w-halo: elements w0+4, w0+5 live in lane+1's registers.
        float a4 = __shfl_down_sync(0xffffffffu, A.x, 1);
        float a5 = __shfl_down_sync(0xffffffffu, A.y, 1);
        float b4 = __shfl_down_sync(0xffffffffu, B.x, 1);
        float p4 = __shfl_down_sync(0xffffffffu, P.x, 1);
        if (lane == 31 && w0 + 5 < WW) {   // cross-warp halo via scalar loads
            a4 = p0[(size_t)h   * WW + w0 + 4];
            a5 = p0[(size_t)h   * WW + w0 + 5];
            b4 = p0[(size_t)hc1 * WW + w0 + 4];
            p4 = p1[(size_t)h   * WW + w0 + 4];
        }
        // (tid==127: w0+4 out of range, but every term touching a4/a5/b4/p4
        //  is masked by the w-validity predicates below.)

        const float wh1 = (h + 1 < HH) ? 1.0f : 0.0f;
        const float wh2 = (h + 2 < HH) ? 1.0f : 0.0f;

        const float av[6] = {A.x, A.y, A.z, A.w, a4, a5};
        const float bv[5] = {B.x, B.y, B.z, B.w, b4};
        const float pv[5] = {P.x, P.y, P.z, P.w, p4};
        const float cv[4] = {C.x, C.y, C.z, C.w};
        const float qv[4] = {Q.x, Q.y, Q.z, Q.w};
        const float rv[4] = {R.x, R.y, R.z, R.w};

        #pragma unroll
        for (int i = 0; i < 4; ++i) {
            const int wi = w0 + i;
            float s = 0.0f;
            if (wi <= WW - 3)   // g_xx
                s += fabsf(av[i] - 2.0f * av[i + 1] + av[i + 2]);
            // g_yy
            s += wh2 * fabsf(av[i] - 2.0f * bv[i] + cv[i]);
            // g_zz (weight CONTIZ^2 = 0.5)
            s += wzz * fabsf(av[i] - 2.0f * pv[i] + qv[i]);
            if (wi <= WW - 2) {
                // g_xy (weight 2)
                s += (2.0f * wh1) * fabsf(av[i] - av[i + 1] - bv[i] + bv[i + 1]);
                // g_xz (weight 2*CONTIZ = sqrt2)
                s += wxz * fabsf(av[i] - av[i + 1] - pv[i] + pv[i + 1]);
            }
            // g_yz (weight 2*CONTIZ = sqrt2)
            s += (wxz * wh1) * fabsf(av[i] - bv[i] - pv[i] + rv[i]);
            acc += s;
        }

        // roll the register rows
        A = B; B = C; P = R;
    }

    // ---- reduction: warp -> block -> global atomic ----
    acc += __shfl_xor_sync(0xffffffffu, acc, 16);
    acc += __shfl_xor_sync(0xffffffffu, acc, 8);
    acc += __shfl_xor_sync(0xffffffffu, acc, 4);
    acc += __shfl_xor_sync(0xffffffffu, acc, 2);
    acc += __shfl_xor_sync(0xffffffffu, acc, 1);

    __shared__ float warpsum[4];
    if (lane == 0) warpsum[tid >> 5] = acc;
    __syncthreads();
    if (tid == 0) {
        const float total = warpsum[0] + warpsum[1] + warpsum[2] + warpsum[3];
        atomicAdd(out, total * (1.0f / ((float)HH * (float)WW)));
    }
}

extern "C" void kernel_launch(void* const* d_in, const int* in_sizes, int n_in,
                              void* d_out, int out_size) {
    const float* img = (const float*)d_in[0];
    float* out = (float*)d_out;
    (void)in_sizes; (void)n_in; (void)out_size;

    hess_init_kernel<<<1, 1>>>(out);
    dim3 grid(HH / HS, DD, NN);   // 16 x 64 x 2 = 2048 blocks
    hess_kernel<<<grid, 128>>>(img, out);
}

// round 3
// speedup vs baseline: 1.1991x; 1.1991x over previous
#include <cuda_runtime.h>

#define WW 512
#define HH 512
#define DD 64
#define NN 2
#define HS 8
#define SQRT2F 1.41421356237309515f

// Zero the scalar output (d_out is poisoned to 0xAA by the harness).
__global__ void hess_init_kernel(float* out) { out[0] = 0.0f; }

// One block = one (n, d) slab pair x one 8-row strip of h. 128 threads,
// each owns 4 consecutive w (float4). Rows AND their w-halos roll through
// registers; per row only slab-d row h+2, slab-d+1 row h+1, slab-d+2 row h
// are loaded fresh. No shuffles, no divergent halo branch.
template<bool BND>
__device__ __forceinline__ float strip_sum(
    const float* __restrict__ p0, const float* __restrict__ p1,
    const float* __restrict__ p2, int h0, int w0, float wzz)
{
    // halo addresses (clamped only for the last thread; its edge terms are masked)
    const int hw2 = (w0 + 5 < WW) ? (w0 + 4) : (WW - 2);  // float2 halo
    const int hw1 = (w0 + 4 < WW) ? (w0 + 4) : (WW - 1);  // scalar halo

    // per-element w-boundary weights (non-1 only for the last thread)
    float wxx[4], wxy[4], wxz[4];
    #pragma unroll
    for (int i = 0; i < 4; ++i) {
        const int wi = w0 + i;
        wxx[i] = (wi <= WW - 3) ? 1.0f   : 0.0f;   // g_xx validity
        wxy[i] = (wi <= WW - 2) ? 2.0f   : 0.0f;   // g_xy weight*validity
        wxz[i] = (wi <= WW - 2) ? SQRT2F : 0.0f;   // g_xz weight*validity
    }

    // preload rolling rows: A=(d,h0), B=(d,h0+1), P=(d+1,h0)  (h0+1<HH always)
    const float* r0a = p0 + (size_t)h0 * WW;
    const float* r0b = p0 + (size_t)(h0 + 1) * WW;
    const float* r1a = p1 + (size_t)h0 * WW;
    float4 A  = *(const float4*)(r0a + w0);
    float2 ah = *(const float2*)(r0a + hw2);
    float4 B  = *(const float4*)(r0b + w0);
    float2 bh = *(const float2*)(r0b + hw2);
    float4 P  = *(const float4*)(r1a + w0);
    float  p4 = r1a[hw1];
    float a4 = ah.x, a5 = ah.y, b4 = bh.x, b5 = bh.y;

    // rolling y-difference u = row(h) - row(h+1) of slab d
    float u[5];
    u[0] = A.x - B.x; u[1] = A.y - B.y; u[2] = A.z - B.z; u[3] = A.w - B.w;
    u[4] = a4 - b4;

    float acc0 = 0.0f, acc1 = 0.0f;

    #pragma unroll 2
    for (int h = h0; h < h0 + HS; ++h) {
        int hc1 = h + 1, hc2 = h + 2;
        float wh1 = 1.0f, wh2 = 1.0f;
        if (BND) {
            if (hc1 > HH - 1) { hc1 = HH - 1; wh1 = 0.0f; }
            if (hc2 > HH - 1) { hc2 = HH - 1; wh2 = 0.0f; }
        }
        const float* rc = p0 + (size_t)hc2 * WW;  // (d,   h+2)
        const float* rr = p1 + (size_t)hc1 * WW;  // (d+1, h+1)
        const float* rq = p2 + (size_t)h   * WW;  // (d+2, h  )
        float4 C  = *(const float4*)(rc + w0);
        float2 ch = *(const float2*)(rc + hw2);
        float4 R  = *(const float4*)(rr + w0);
        float  r4 = rr[hw1];
        float4 Q  = *(const float4*)(rq + w0);

        // shared differences
        float un[5], v[5], z[4], s[4], dx[5];
        un[0] = B.x - C.x; un[1] = B.y - C.y; un[2] = B.z - C.z; un[3] = B.w - C.w;
        un[4] = b4 - ch.x;
        v[0] = A.x - P.x; v[1] = A.y - P.y; v[2] = A.z - P.z; v[3] = A.w - P.w;
        v[4] = a4 - p4;
        z[0] = P.x - Q.x; z[1] = P.y - Q.y; z[2] = P.z - Q.z; z[3] = P.w - Q.w;
        s[0] = P.x - R.x; s[1] = P.y - R.y; s[2] = P.z - R.z; s[3] = P.w - R.w;
        dx[0] = A.x - A.y; dx[1] = A.y - A.z; dx[2] = A.z - A.w;
        dx[3] = A.w - a4;  dx[4] = a4 - a5;

        const float wyy = BND ? wh2 : 1.0f;
        const float wyz = BND ? (SQRT2F * wh1) : SQRT2F;

        #pragma unroll
        for (int i = 0; i < 4; ++i) {
            const float wxyi = BND ? (wxy[i] * wh1) : wxy[i];
            acc0 = fmaf(wxx[i], fabsf(dx[i] - dx[i + 1]), acc0);  // g_xx
            acc1 = fmaf(wyy,    fabsf(u[i]  - un[i]),     acc1);  // g_yy
            acc0 = fmaf(wzz,    fabsf(v[i]  - z[i]),      acc0);  // g_zz * 0.5
            acc1 = fmaf(wxyi,   fabsf(u[i]  - u[i + 1]),  acc1);  // g_xy * 2
            acc0 = fmaf(wxz[i], fabsf(v[i]  - v[i + 1]),  acc0);  // g_xz * sqrt2
            acc1 = fmaf(wyz,    fabsf(u[i]  - s[i]),      acc1);  // g_yz * sqrt2
        }

        // roll rows + halos + u
        A = B; B = C;
        a4 = b4; a5 = b5; b4 = ch.x; b5 = ch.y;
        P = R; p4 = r4;
        u[0] = un[0]; u[1] = un[1]; u[2] = un[2]; u[3] = un[3]; u[4] = un[4];
    }
    return acc0 + acc1;
}

__global__ __launch_bounds__(128)
void hess_kernel(const float* __restrict__ x, float* __restrict__ out) {
    const int tid = threadIdx.x;
    const int lane = tid & 31;
    const int w0 = tid << 2;                 // 128 * 4 = 512 = WW
    const int h0 = blockIdx.x * HS;
    const int d  = blockIdx.y;
    const int n  = blockIdx.z;

    const size_t slab = (size_t)HH * WW;
    const float* p0 = x + (size_t)(n * DD + d) * slab;
    const bool hd1 = (d + 1 < DD);
    const bool hd2 = (d + 2 < DD);
    const float* p1 = p0 + (hd1 ? slab : 0);  // clamped: auto-zeroes xz/yz edge terms
    const float* p2 = p1 + (hd2 ? slab : 0);
    const float wzz = hd2 ? 0.5f : 0.0f;      // CONTIZ^2, masks g_zz at d edge

    float acc;
    if (blockIdx.x != (HH / HS - 1))
        acc = strip_sum<false>(p0, p1, p2, h0, w0, wzz);
    else
        acc = strip_sum<true>(p0, p1, p2, h0, w0, wzz);

    // ---- reduction: warp -> block -> global atomic ----
    acc += __shfl_xor_sync(0xffffffffu, acc, 16);
    acc += __shfl_xor_sync(0xffffffffu, acc, 8);
    acc += __shfl_xor_sync(0xffffffffu, acc, 4);
    acc += __shfl_xor_sync(0xffffffffu, acc, 2);
    acc += __shfl_xor_sync(0xffffffffu, acc, 1);

    __shared__ float warpsum[4];
    if (lane == 0) warpsum[tid >> 5] = acc;
    __syncthreads();
    if (tid == 0) {
        const float total = warpsum[0] + warpsum[1] + warpsum[2] + warpsum[3];
        atomicAdd(out, total * (1.0f / ((float)HH * (float)WW)));
    }
}

extern "C" void kernel_launch(void* const* d_in, const int* in_sizes, int n_in,
                              void* d_out, int out_size) {
    const float* img = (const float*)d_in[0];
    float* out = (float*)d_out;
    (void)in_sizes; (void)n_in; (void)out_size;

    hess_init_kernel<<<1, 1>>>(out);
    dim3 grid(HH / HS, DD, NN);   // 64 x 64 x 2 = 8192 blocks
    hess_kernel<<<grid, 128>>>(img, out);
}

// round 4
// speedup vs baseline: 1.5947x; 1.3299x over previous
#include <cuda_runtime.h>

#define WW 512
#define HH 512
#define DD 64
#define NN 2
#define HS 8
#define SQRT2F 1.41421356237309515f

// Zero the scalar output (d_out is poisoned to 0xAA by the harness).
__global__ void hess_init_kernel(float* out) { out[0] = 0.0f; }

// One block = one (n, d) slab pair x one 8-row strip of h. 128 threads,
// each owns 4 consecutive w (float4). Fully unrolled over the 8 rows:
// every load address is base + compile-time offset, so ptxas batches the
// loads ahead of their consumers (software pipelining for free) and all
// per-row address arithmetic disappears into LDG immediates.
template<bool BND>
__device__ __forceinline__ float strip_sum(
    const float* __restrict__ p0, const float* __restrict__ p1,
    const float* __restrict__ p2, int h0, int w0, float wzz)
{
    // halo addresses (clamped only for the last thread; its edge terms are masked)
    const int hw2 = (w0 + 5 < WW) ? (w0 + 4) : (WW - 2);  // float2 halo
    const int hw1 = (w0 + 4 < WW) ? (w0 + 4) : (WW - 1);  // scalar halo

    // per-element w-boundary weights (non-1 only for the last thread)
    float wxx[4], wxy[4], wxz[4];
    #pragma unroll
    for (int i = 0; i < 4; ++i) {
        const int wi = w0 + i;
        wxx[i] = (wi <= WW - 3) ? 1.0f   : 0.0f;   // g_xx validity
        wxy[i] = (wi <= WW - 2) ? 2.0f   : 0.0f;   // g_xy weight*validity
        wxz[i] = (wi <= WW - 2) ? SQRT2F : 0.0f;   // g_xz weight*validity
    }

    // fixed base pointers (32-bit offsets; all later offsets are constants)
    const float* ra  = p0 + h0 * WW;   // slab d,   row h0
    const float* rp  = p1 + h0 * WW;   // slab d+1, row h0
    const float* rq0 = p2 + h0 * WW;   // slab d+2, row h0

    // preload rolling rows: A=(d,h0), B=(d,h0+1), P=(d+1,h0)  (h0+1<HH always)
    float4 A  = *(const float4*)(ra + w0);
    float2 ah = *(const float2*)(ra + hw2);
    float4 B  = *(const float4*)(ra + WW + w0);
    float2 bh = *(const float2*)(ra + WW + hw2);
    float4 P  = *(const float4*)(rp + w0);
    float  p4 = rp[hw1];
    float a4 = ah.x, a5 = ah.y, b4 = bh.x, b5 = bh.y;

    // rolling y-difference u = row(h) - row(h+1) of slab d
    float u[5];
    u[0] = A.x - B.x; u[1] = A.y - B.y; u[2] = A.z - B.z; u[3] = A.w - B.w;
    u[4] = a4 - b4;

    float acc0 = 0.0f, acc1 = 0.0f;

    #pragma unroll
    for (int j = 0; j < HS; ++j) {
        // compile-time boundary clamps (last strip only): keep loads in
        // bounds; the clamped values are killed by zero weights.
        int ec = 0, er = 0;
        float wh2 = 1.0f, wh1 = 1.0f;
        if (BND) {
            if (j >= HS - 2) { ec = j - (HS - 3); wh2 = 0.0f; }
            if (j >= HS - 1) { er = 1;            wh1 = 0.0f; }
        }
        const float* rc  = ra  + (j + 2 - ec) * WW;  // (d,   h+2)
        const float* rr  = rp  + (j + 1 - er) * WW;  // (d+1, h+1)
        const float* rqj = rq0 + j * WW;             // (d+2, h  )

        float4 C  = *(const float4*)(rc + w0);
        float2 ch = *(const float2*)(rc + hw2);
        float4 R  = *(const float4*)(rr + w0);
        float  r4 = rr[hw1];
        float4 Q  = *(const float4*)(rqj + w0);

        // shared differences
        float un[5], v[5], z[4], s[4], dx[5];
        un[0] = B.x - C.x; un[1] = B.y - C.y; un[2] = B.z - C.z; un[3] = B.w - C.w;
        un[4] = b4 - ch.x;
        v[0] = A.x - P.x; v[1] = A.y - P.y; v[2] = A.z - P.z; v[3] = A.w - P.w;
        v[4] = a4 - p4;
        z[0] = P.x - Q.x; z[1] = P.y - Q.y; z[2] = P.z - Q.z; z[3] = P.w - Q.w;
        s[0] = P.x - R.x; s[1] = P.y - R.y; s[2] = P.z - R.z; s[3] = P.w - R.w;
        dx[0] = A.x - A.y; dx[1] = A.y - A.z; dx[2] = A.z - A.w;
        dx[3] = A.w - a4;  dx[4] = a4 - a5;

        const float wyy = BND ? wh2 : 1.0f;
        const float wyz = BND ? (SQRT2F * wh1) : SQRT2F;

        #pragma unroll
        for (int i = 0; i < 4; ++i) {
            const float wxyi = BND ? (wxy[i] * wh1) : wxy[i];
            acc0 = fmaf(wxx[i], fabsf(dx[i] - dx[i + 1]), acc0);  // g_xx
            acc1 = fmaf(wyy,    fabsf(u[i]  - un[i]),     acc1);  // g_yy
            acc0 = fmaf(wzz,    fabsf(v[i]  - z[i]),      acc0);  // g_zz * 0.5
            acc1 = fmaf(wxyi,   fabsf(u[i]  - u[i + 1]),  acc1);  // g_xy * 2
            acc0 = fmaf(wxz[i], fabsf(v[i]  - v[i + 1]),  acc0);  // g_xz * sqrt2
            acc1 = fmaf(wyz,    fabsf(u[i]  - s[i]),      acc1);  // g_yz * sqrt2
        }

        // roll rows + halos + u (pure register renames under full unroll)
        A = B; B = C;
        a4 = b4; a5 = b5; b4 = ch.x; b5 = ch.y;
        P = R; p4 = r4;
        u[0] = un[0]; u[1] = un[1]; u[2] = un[2]; u[3] = un[3]; u[4] = un[4];
    }
    return acc0 + acc1;
}

__global__ __launch_bounds__(128, 8)
void hess_kernel(const float* __restrict__ x, float* __restrict__ out) {
    const int tid = threadIdx.x;
    const int lane = tid & 31;
    const int w0 = tid << 2;                 // 128 * 4 = 512 = WW
    const int h0 = blockIdx.x * HS;
    const int d  = blockIdx.y;
    const int n  = blockIdx.z;

    const size_t slab = (size_t)HH * WW;
    const float* p0 = x + (size_t)(n * DD + d) * slab;
    const bool hd1 = (d + 1 < DD);
    const bool hd2 = (d + 2 < DD);
    const float* p1 = p0 + (hd1 ? slab : 0);  // clamped: auto-zeroes xz/yz edge terms
    const float* p2 = p1 + (hd2 ? slab : 0);
    const float wzz = hd2 ? 0.5f : 0.0f;      // CONTIZ^2, masks g_zz at d edge

    float acc;
    if (blockIdx.x != (HH / HS - 1))
        acc = strip_sum<false>(p0, p1, p2, h0, w0, wzz);
    else
        acc = strip_sum<true>(p0, p1, p2, h0, w0, wzz);

    // ---- reduction: warp -> block -> global atomic ----
    acc += __shfl_xor_sync(0xffffffffu, acc, 16);
    acc += __shfl_xor_sync(0xffffffffu, acc, 8);
    acc += __shfl_xor_sync(0xffffffffu, acc, 4);
    acc += __shfl_xor_sync(0xffffffffu, acc, 2);
    acc += __shfl_xor_sync(0xffffffffu, acc, 1);

    __shared__ float warpsum[4];
    if (lane == 0) warpsum[tid >> 5] = acc;
    __syncthreads();
    if (tid == 0) {
        const float total = warpsum[0] + warpsum[1] + warpsum[2] + warpsum[3];
        atomicAdd(out, total * (1.0f / ((float)HH * (float)WW)));
    }
}

extern "C" void kernel_launch(void* const* d_in, const int* in_sizes, int n_in,
                              void* d_out, int out_size) {
    const float* img = (const float*)d_in[0];
    float* out = (float*)d_out;
    (void)in_sizes; (void)n_in; (void)out_size;

    hess_init_kernel<<<1, 1>>>(out);
    dim3 grid(HH / HS, DD, NN);   // 64 x 64 x 2 = 8192 blocks
    hess_kernel<<<grid, 128>>>(img, out);
}